// round 16
// baseline (speedup 1.0000x reference)
#include <cuda_runtime.h>
#include <cuda_fp16.h>
#include <mma.h>
#include <cstdint>
#include <cstddef>

using namespace nvcuda;

#define N_NODES  100000
#define N_PAD    100096   // multiple of 128
#define N_EDGES  1600000
#define DIM      128
#define N_GRAPHS 512

// ---------------- scratch ----------------
__device__ __align__(16) __half g_h16[(size_t)N_NODES * DIM];   // gemm out (gather src)
__device__ __align__(16) __half g_h16b[(size_t)N_PAD * DIM];    // agg1/agg2 out (gemm2 A)
__device__ __align__(16) __half g_w16[2][DIM * DIM];            // fp16 W1, W2 row-major
__device__ __align__(16) float  g_dinv[N_NODES];
__device__ __align__(16) int    g_cnt[N_NODES];
__device__ __align__(16) int    g_off[N_NODES];                 // after fill: segment END
__device__ __align__(16) int    g_csr_i[N_EDGES];               // src index only
__device__ __align__(16) float  g_gsum[N_GRAPHS * DIM];
__device__ __align__(16) float  g_gcnt[N_GRAPHS];
__device__ int g_partial[32];

// ---------------- setup ----------------
__global__ void k_zero_cnt() {
    int i = blockIdx.x * blockDim.x + threadIdx.x;
    if (i < N_NODES) g_cnt[i] = 0;
}
__global__ void k_zero_g() {
    int i = blockIdx.x * blockDim.x + threadIdx.x;
    if (i < N_GRAPHS * DIM) g_gsum[i] = 0.f;
    if (i < N_GRAPHS) g_gcnt[i] = 0.f;
}

__global__ __launch_bounds__(256) void k_prepw(const float* __restrict__ Wa,
                                               const float* __restrict__ Wb) {
    int w = blockIdx.x >> 3;
    const float* W = w ? Wb : Wa;
    __half* o = g_w16[w];
    int i = (blockIdx.x & 7) * 2048 + threadIdx.x * 8;
    float4 v0 = *(const float4*)(W + i);
    float4 v1 = *(const float4*)(W + i + 4);
    __half2 h0 = __floats2half2_rn(v0.x, v0.y);
    __half2 h1 = __floats2half2_rn(v0.z, v0.w);
    __half2 h2 = __floats2half2_rn(v1.x, v1.y);
    __half2 h3 = __floats2half2_rn(v1.z, v1.w);
    uint4 ov;
    ov.x = *(unsigned*)&h0; ov.y = *(unsigned*)&h1;
    ov.z = *(unsigned*)&h2; ov.w = *(unsigned*)&h3;
    *(uint4*)(o + i) = ov;
}

__global__ void k_degree(const int* __restrict__ ei) {
    int e4 = (blockIdx.x * blockDim.x + threadIdx.x) * 4;
    if (e4 + 3 < N_EDGES) {
        int4 d = *(const int4*)(ei + N_EDGES + e4);
        if ((unsigned)d.x < N_NODES) atomicAdd(&g_cnt[d.x], 1);
        if ((unsigned)d.y < N_NODES) atomicAdd(&g_cnt[d.y], 1);
        if ((unsigned)d.z < N_NODES) atomicAdd(&g_cnt[d.z], 1);
        if ((unsigned)d.w < N_NODES) atomicAdd(&g_cnt[d.w], 1);
    }
}

__global__ __launch_bounds__(1024) void k_scan1() {
    __shared__ int warp_sums[32];
    int t = threadIdx.x, lane = t & 31, wid = t >> 5;
    int i0 = blockIdx.x * 4096 + t * 4;
    int v[4];
#pragma unroll
    for (int q = 0; q < 4; q++) {
        int i = i0 + q;
        v[q] = (i < N_NODES) ? g_cnt[i] : 0;
        if (i < N_NODES) g_dinv[i] = rsqrtf((float)v[q] + 1.0f);
    }
    int tsum = v[0] + v[1] + v[2] + v[3];
    int x = tsum;
#pragma unroll
    for (int s = 1; s < 32; s <<= 1) {
        int y = __shfl_up_sync(0xffffffffu, x, s);
        if (lane >= s) x += y;
    }
    if (lane == 31) warp_sums[wid] = x;
    __syncthreads();
    if (wid == 0) {
        int ws = warp_sums[lane];
        int xx = ws;
#pragma unroll
        for (int s = 1; s < 32; s <<= 1) {
            int y = __shfl_up_sync(0xffffffffu, xx, s);
            if (lane >= s) xx += y;
        }
        warp_sums[lane] = xx - ws;
    }
    __syncthreads();
    int run = warp_sums[wid] + (x - tsum);
#pragma unroll
    for (int q = 0; q < 4; q++) {
        int i = i0 + q;
        if (i < N_NODES) g_off[i] = run;
        run += v[q];
    }
    if (t == 1023) g_partial[blockIdx.x] = warp_sums[31] + x;
}

__global__ void k_scan3(int nblk) {
    __shared__ int sp[32];
    int t = threadIdx.x;
    if (t < 32) {
        int v = (t < nblk) ? g_partial[t] : 0;
        int x = v;
#pragma unroll
        for (int s = 1; s < 32; s <<= 1) {
            int y = __shfl_up_sync(0xffffffffu, x, s);
            if ((t & 31) >= s) x += y;
        }
        sp[t] = x - v;
    }
    __syncthreads();
    int i = blockIdx.x * blockDim.x + t;
    if (i < N_NODES) g_off[i] += sp[i >> 12];
}

// fill uses g_off as live cursors; after fill, g_off[n] = segment end.
__global__ void k_fill(const int* __restrict__ ei) {
    int e4 = (blockIdx.x * blockDim.x + threadIdx.x) * 4;
    if (e4 + 3 < N_EDGES) {
        int4 s = *(const int4*)(ei + e4);
        int4 d = *(const int4*)(ei + N_EDGES + e4);
        int ss[4] = {s.x, s.y, s.z, s.w};
        int dd[4] = {d.x, d.y, d.z, d.w};
#pragma unroll
        for (int q = 0; q < 4; q++) {
            if ((unsigned)ss[q] < N_NODES && (unsigned)dd[q] < N_NODES) {
                int pos = atomicAdd(&g_off[dd[q]], 1);
                if ((unsigned)pos < N_EDGES) g_csr_i[pos] = ss[q];
            }
        }
    }
}

// scale g_h16 rows by dinv[row] (8 halfs per thread)
__global__ void k_scale() {
    size_t i4 = (size_t)blockIdx.x * blockDim.x + threadIdx.x;  // uint4 index
    if (i4 < (size_t)N_NODES * 16) {
        int row = (int)(i4 >> 4);
        float dv = g_dinv[row];
        uint4 v = ((const uint4*)g_h16)[i4];
        float2 f0 = __half22float2(*(__half2*)&v.x);
        float2 f1 = __half22float2(*(__half2*)&v.y);
        float2 f2 = __half22float2(*(__half2*)&v.z);
        float2 f3 = __half22float2(*(__half2*)&v.w);
        __half2 h0 = __floats2half2_rn(f0.x * dv, f0.y * dv);
        __half2 h1 = __floats2half2_rn(f1.x * dv, f1.y * dv);
        __half2 h2 = __floats2half2_rn(f2.x * dv, f2.y * dv);
        __half2 h3 = __floats2half2_rn(f3.x * dv, f3.y * dv);
        uint4 o;
        o.x = *(unsigned*)&h0; o.y = *(unsigned*)&h1;
        o.z = *(unsigned*)&h2; o.w = *(unsigned*)&h3;
        ((uint4*)g_h16)[i4] = o;
    }
}

// ---------------- wmma GEMM: g_h16 = fp16( [dinv?] * (A @ W16[widx]) ) ------------
// do_scale=0: write raw (dinv applied later by k_scale). do_scale=1: fuse dinv.
#define WLD 136
#define XLD 136
__global__ __launch_bounds__(256, 2) void k_gemm_w(const float* __restrict__ xin,
                                                   int a_sel, int widx, int do_scale) {
    __shared__ __align__(16) __half Ws[DIM * WLD];
    __shared__ __align__(16) __half Xs[DIM * XLD];
    int tid = threadIdx.x;
    int wid = tid >> 5, lane = tid & 31;
    int wm = wid & 3;
    int wn = wid >> 2;
    int r0 = blockIdx.x * 128;

    {
        const uint4* src = (const uint4*)g_w16[widx];
#pragma unroll
        for (int it = 0; it < 8; it++) {
            int i = tid + it * 256;
            int row = i >> 4, col8 = (i & 15) << 3;
            *(uint4*)(Ws + row * WLD + col8) = src[i];
        }
    }

    if (a_sel == 0) {
        const float4* x4 = (const float4*)(xin + (size_t)r0 * DIM);
        bool full = (r0 + 128) <= N_NODES;
#pragma unroll
        for (int it = 0; it < 16; it++) {
            int j = tid + it * 256;
            int row = j >> 5, col4 = (j & 31) << 2;
            float4 v = make_float4(0.f, 0.f, 0.f, 0.f);
            if (full || (r0 + row) < N_NODES) v = x4[j];
            __half2 h0 = __floats2half2_rn(v.x, v.y);
            __half2 h1 = __floats2half2_rn(v.z, v.w);
            uint2 o;
            o.x = *(unsigned*)&h0; o.y = *(unsigned*)&h1;
            *(uint2*)(Xs + row * XLD + col4) = o;
        }
    } else {
        const uint4* src = (const uint4*)(g_h16b + (size_t)r0 * DIM);
#pragma unroll
        for (int it = 0; it < 8; it++) {
            int i = tid + it * 256;
            int row = i >> 4, col8 = (i & 15) << 3;
            *(uint4*)(Xs + row * XLD + col8) = src[i];
        }
    }
    __syncthreads();

    wmma::fragment<wmma::accumulator, 16, 16, 16, float> acc[2][4];
#pragma unroll
    for (int mi = 0; mi < 2; mi++)
#pragma unroll
        for (int ni = 0; ni < 4; ni++) wmma::fill_fragment(acc[mi][ni], 0.f);

#pragma unroll
    for (int k = 0; k < 8; k++) {
        wmma::fragment<wmma::matrix_a, 16, 16, 16, __half, wmma::row_major> af[2];
#pragma unroll
        for (int mi = 0; mi < 2; mi++)
            wmma::load_matrix_sync(af[mi], Xs + (wm * 32 + mi * 16) * XLD + k * 16, XLD);
#pragma unroll
        for (int ni = 0; ni < 4; ni++) {
            wmma::fragment<wmma::matrix_b, 16, 16, 16, __half, wmma::row_major> bf;
            wmma::load_matrix_sync(bf, Ws + (k * 16) * WLD + wn * 64 + ni * 16, WLD);
#pragma unroll
            for (int mi = 0; mi < 2; mi++)
                wmma::mma_sync(acc[mi][ni], af[mi], bf, acc[mi][ni]);
        }
    }
    __syncthreads();

    float* Cs = (float*)Ws + wid * 1024;
#pragma unroll
    for (int mi = 0; mi < 2; mi++) {
#pragma unroll
        for (int ni = 0; ni < 4; ni++)
            wmma::store_matrix_sync(Cs + ni * 16, acc[mi][ni], 64, wmma::mem_row_major);
        __syncwarp();
        int r = lane >> 1;
        int cb = (lane & 1) * 32;
        int grow = r0 + wm * 32 + mi * 16 + r;
        if (grow < N_NODES) {
            float dv = do_scale ? g_dinv[grow] : 1.0f;
            const float* srcr = Cs + r * 64 + cb;
            __half* dstp = g_h16 + (size_t)grow * DIM + wn * 64 + cb;
#pragma unroll
            for (int j = 0; j < 32; j += 8) {
                float4 v0 = *(const float4*)(srcr + j);
                float4 v1 = *(const float4*)(srcr + j + 4);
                __half2 h0 = __floats2half2_rn(v0.x * dv, v0.y * dv);
                __half2 h1 = __floats2half2_rn(v0.z * dv, v0.w * dv);
                __half2 h2 = __floats2half2_rn(v1.x * dv, v1.y * dv);
                __half2 h3 = __floats2half2_rn(v1.z * dv, v1.w * dv);
                uint4 o;
                o.x = *(unsigned*)&h0; o.y = *(unsigned*)&h1;
                o.z = *(unsigned*)&h2; o.w = *(unsigned*)&h3;
                *(uint4*)(dstp + j) = o;
            }
        }
        __syncwarp();
    }
}

// ---------------- per-node gather core (all 32 lanes end with the full acc) --------
__device__ __forceinline__ void acc_row(float* acc, const uint4& r) {
    float2 f0 = __half22float2(*(__half2*)&r.x);
    float2 f1 = __half22float2(*(__half2*)&r.y);
    float2 f2 = __half22float2(*(__half2*)&r.z);
    float2 f3 = __half22float2(*(__half2*)&r.w);
    acc[0] += f0.x; acc[1] += f0.y; acc[2] += f1.x; acc[3] += f1.y;
    acc[4] += f2.x; acc[5] += f2.y; acc[6] += f3.x; acc[7] += f3.y;
}

__device__ __forceinline__ void gather_node(const uint4* __restrict__ in4, int n,
                                            int half, int hl, float* acc) {
    float acca[8], accb[8];
    {
        uint4 sv = __ldcg(&in4[(size_t)n * 16 + hl]);
        float2 f0 = __half22float2(*(__half2*)&sv.x);
        float2 f1 = __half22float2(*(__half2*)&sv.y);
        float2 f2 = __half22float2(*(__half2*)&sv.z);
        float2 f3 = __half22float2(*(__half2*)&sv.w);
        float m = (half == 0) ? 1.f : 0.f;
        acca[0] = m * f0.x; acca[1] = m * f0.y; acca[2] = m * f1.x; acca[3] = m * f1.y;
        acca[4] = m * f2.x; acca[5] = m * f2.y; acca[6] = m * f3.x; acca[7] = m * f3.y;
#pragma unroll
        for (int q = 0; q < 8; q++) accb[q] = 0.f;
    }
    int end = g_off[n];
    int j = end - g_cnt[n];
    for (; j + 16 <= end; j += 16) {
        int s0 = __ldcs(&g_csr_i[j + half]);
        int s1 = __ldcs(&g_csr_i[j + 2 + half]);
        int s2 = __ldcs(&g_csr_i[j + 4 + half]);
        int s3 = __ldcs(&g_csr_i[j + 6 + half]);
        int s4 = __ldcs(&g_csr_i[j + 8 + half]);
        int s5 = __ldcs(&g_csr_i[j + 10 + half]);
        int s6 = __ldcs(&g_csr_i[j + 12 + half]);
        int s7 = __ldcs(&g_csr_i[j + 14 + half]);
        uint4 r0 = __ldcg(&in4[(size_t)s0 * 16 + hl]);
        uint4 r1 = __ldcg(&in4[(size_t)s1 * 16 + hl]);
        uint4 r2 = __ldcg(&in4[(size_t)s2 * 16 + hl]);
        uint4 r3 = __ldcg(&in4[(size_t)s3 * 16 + hl]);
        uint4 r4 = __ldcg(&in4[(size_t)s4 * 16 + hl]);
        uint4 r5 = __ldcg(&in4[(size_t)s5 * 16 + hl]);
        uint4 r6 = __ldcg(&in4[(size_t)s6 * 16 + hl]);
        uint4 r7 = __ldcg(&in4[(size_t)s7 * 16 + hl]);
        acc_row(acca, r0); acc_row(accb, r1);
        acc_row(acca, r2); acc_row(accb, r3);
        acc_row(acca, r4); acc_row(accb, r5);
        acc_row(acca, r6); acc_row(accb, r7);
    }
    for (; j + 4 <= end; j += 4) {
        int s0 = __ldcs(&g_csr_i[j + half]);
        int s1 = __ldcs(&g_csr_i[j + 2 + half]);
        uint4 r0 = __ldcg(&in4[(size_t)s0 * 16 + hl]);
        uint4 r1 = __ldcg(&in4[(size_t)s1 * 16 + hl]);
        acc_row(acca, r0); acc_row(accb, r1);
    }
    for (; j + 2 <= end; j += 2) {
        int s = __ldcs(&g_csr_i[j + half]);
        uint4 r = __ldcg(&in4[(size_t)s * 16 + hl]);
        acc_row(acca, r);
    }
    if (j + half < end) {
        int s = __ldcs(&g_csr_i[j + half]);
        uint4 r = __ldcg(&in4[(size_t)s * 16 + hl]);
        acc_row(accb, r);
    }
#pragma unroll
    for (int q = 0; q < 8; q++) {
        float v = acca[q] + accb[q];
        acc[q] = v + __shfl_xor_sync(0xffffffffu, v, 16);
    }
}

// ---------------- agg (layers 1 & 2): fp16 out with fused bias/relu/scale ----------
__global__ __launch_bounds__(256) void k_agg(int in_sel, int out_scale,
                                             const float* __restrict__ bias) {
    int n = (blockIdx.x * blockDim.x + threadIdx.x) >> 5;
    int lane = threadIdx.x & 31;
    if (n >= N_NODES) return;
    int half = lane >> 4, hl = lane & 15;
    const uint4* in4 = (const uint4*)(in_sel ? g_h16b : g_h16);
    float dn = g_dinv[n];

    float acc[8];
    gather_node(in4, n, half, hl, acc);

    if (half == 0) {
#pragma unroll
        for (int q = 0; q < 8; q++) acc[q] *= dn;
        float4 b0 = *(const float4*)(bias + hl * 8);
        float4 b1 = *(const float4*)(bias + hl * 8 + 4);
        acc[0] = fmaxf(acc[0] + b0.x, 0.f); acc[1] = fmaxf(acc[1] + b0.y, 0.f);
        acc[2] = fmaxf(acc[2] + b0.z, 0.f); acc[3] = fmaxf(acc[3] + b0.w, 0.f);
        acc[4] = fmaxf(acc[4] + b1.x, 0.f); acc[5] = fmaxf(acc[5] + b1.y, 0.f);
        acc[6] = fmaxf(acc[6] + b1.z, 0.f); acc[7] = fmaxf(acc[7] + b1.w, 0.f);
        if (out_scale) {
#pragma unroll
            for (int q = 0; q < 8; q++) acc[q] *= dn;
        }
        __half2 h0 = __floats2half2_rn(acc[0], acc[1]);
        __half2 h1 = __floats2half2_rn(acc[2], acc[3]);
        __half2 h2 = __floats2half2_rn(acc[4], acc[5]);
        __half2 h3 = __floats2half2_rn(acc[6], acc[7]);
        uint4 o;
        o.x = *(unsigned*)&h0; o.y = *(unsigned*)&h1;
        o.z = *(unsigned*)&h2; o.w = *(unsigned*)&h3;
        *(uint4*)(g_h16b + (size_t)n * DIM + hl * 8) = o;
    }
}

// ---------------- agg3 + readout fused: warp = 8 consecutive nodes -----------------
#define POOL_NPW 8
__global__ __launch_bounds__(256) void k_agg_pool(const int* __restrict__ batch) {
    int warp = (blockIdx.x * blockDim.x + threadIdx.x) >> 5;
    int lane = threadIdx.x & 31;
    int half = lane >> 4, hl = lane & 15;
    int nbase = warp * POOL_NPW;
    if (nbase >= N_NODES) return;
    const uint4* in4 = (const uint4*)g_h16b;

    float racc[8];
#pragma unroll
    for (int q = 0; q < 8; q++) racc[q] = 0.f;
    int gprev = -1, rcnt = 0;

    for (int i = 0; i < POOL_NPW; i++) {
        int n = nbase + i;
        if (n >= N_NODES) break;
        int b = batch[n];
        if ((unsigned)b >= N_GRAPHS) b = 0;
        if (b != gprev) {
            if (gprev >= 0) {
                int d = hl * 8 + half * 4;
#pragma unroll
                for (int q = 0; q < 4; q++)
                    atomicAdd(&g_gsum[gprev * DIM + d + q], racc[half * 4 + q]);
                if (lane == 0) atomicAdd(&g_gcnt[gprev], (float)rcnt);
            }
#pragma unroll
            for (int q = 0; q < 8; q++) racc[q] = 0.f;
            rcnt = 0;
            gprev = b;
        }
        float acc[8];
        gather_node(in4, n, half, hl, acc);
        float dn = g_dinv[n];
#pragma unroll
        for (int q = 0; q < 8; q++) racc[q] += dn * acc[q];
        rcnt++;
    }
    if (gprev >= 0) {
        int d = hl * 8 + half * 4;
#pragma unroll
        for (int q = 0; q < 4; q++)
            atomicAdd(&g_gsum[gprev * DIM + d + q], racc[half * 4 + q]);
        if (lane == 0) atomicAdd(&g_gcnt[gprev], (float)rcnt);
    }
}

// ---------------- final ----------------
__global__ __launch_bounds__(128) void k_final(const float* __restrict__ W3,
                                               const float* __restrict__ b3,
                                               float* __restrict__ out) {
    __shared__ float m[DIM];
    int g = blockIdx.x;
    int d = threadIdx.x;
    float c = g_gcnt[g];
    float inv = (c > 0.f) ? (1.f / c) : 0.f;
    m[d] = g_gsum[g * DIM + d] * inv;
    __syncthreads();
    float acc = 0.f;
#pragma unroll 8
    for (int k = 0; k < DIM; k++)
        acc = fmaf(m[k], W3[k * DIM + d], acc);
    out[g * DIM + d] = (c > 0.f) ? (acc + b3[d]) : 0.f;
}

// ---------------- launch: gemm1 fully off the critical path -----------------
extern "C" void kernel_launch(void* const* d_in, const int* in_sizes, int n_in,
                              void* d_out, int out_size) {
    (void)in_sizes; (void)n_in; (void)out_size;
    const float* x     = (const float*)d_in[0];
    const int*   ei    = (const int*)d_in[1];
    const int*   batch = (const int*)d_in[2];
    const float* W1    = (const float*)d_in[3];
    const float* b1    = (const float*)d_in[4];
    const float* W2    = (const float*)d_in[5];
    const float* b2    = (const float*)d_in[6];
    const float* W3    = (const float*)d_in[7];
    const float* b3    = (const float*)d_in[8];
    float* out = (float*)d_out;

    int scan_blocks = (N_NODES + 4095) / 4096;
    int gemm_blocks = (N_NODES + 127) / 128;
    int agg_blocks = (N_NODES * 32 + 255) / 256;
    int pool_blocks = (N_NODES + 8 * POOL_NPW - 1) / (8 * POOL_NPW);
    int scale_blocks = (N_NODES * 16 + 255) / 256;

    cudaStream_t s2;
    cudaStreamCreateWithFlags(&s2, cudaStreamNonBlocking);
    cudaEvent_t ev_fork, ev_dinv, ev_scale;
    cudaEventCreateWithFlags(&ev_fork, cudaEventDisableTiming);
    cudaEventCreateWithFlags(&ev_dinv, cudaEventDisableTiming);
    cudaEventCreateWithFlags(&ev_scale, cudaEventDisableTiming);

    // s2: prepw -> gemm1 (unscaled; needs only x + W1) start immediately
    cudaEventRecord(ev_fork, 0);
    cudaStreamWaitEvent(s2, ev_fork, 0);
    k_prepw<<<16, 256, 0, s2>>>(W1, W2);
    k_gemm_w<<<gemm_blocks, 256, 0, s2>>>(x, 0, 0, /*do_scale=*/0);

    // main: CSR setup chain
    k_zero_cnt<<<(N_NODES + 255) / 256, 256>>>();
    k_degree<<<(N_EDGES / 4 + 255) / 256, 256>>>(ei);
    k_scan1<<<scan_blocks, 1024>>>();
    cudaEventRecord(ev_dinv, 0);

    // s2: scale gemm1 output by dinv (needs dinv + gemm1), then zero pool buffers
    cudaStreamWaitEvent(s2, ev_dinv, 0);
    k_scale<<<scale_blocks, 256, 0, s2>>>();
    k_zero_g<<<(N_GRAPHS * DIM + 255) / 256, 256, 0, s2>>>();
    cudaEventRecord(ev_scale, s2);

    // main continues CSR build concurrently
    k_scan3<<<(N_NODES + 255) / 256, 256>>>(scan_blocks);
    k_fill<<<(N_EDGES / 4 + 255) / 256, 256>>>(ei);

    // join: agg1 needs scaled g_h16 + CSR
    cudaStreamWaitEvent(0, ev_scale, 0);

    // layer 1: agg(g_h16) -> g_h16b = relu(dn*acc + b1)
    k_agg<<<agg_blocks, 256>>>(0, 0, b1);
    // layer 2: gemm2 -> g_h16 (fused dinv) ; agg -> g_h16b = relu(dn*acc + b2) * dn
    k_gemm_w<<<gemm_blocks, 256>>>(x, 1, 1, /*do_scale=*/1);
    k_agg<<<agg_blocks, 256>>>(0, 1, b2);
    // layer 3 + readout fused
    k_agg_pool<<<pool_blocks, 256>>>(batch);

    k_final<<<N_GRAPHS, 128>>>(W3, b3, out);
}